// round 8
// baseline (speedup 1.0000x reference)
#include <cuda_runtime.h>
#include <math_constants.h>

#define B_DIM 8
#define S_DIM 4096
#define H_DIM 1024
#define N_SPANS 100
#define MAX_LEN 64
#define CHUNK 16
#define N_CHUNKS (MAX_LEN / CHUNK)   // 4

#define W (H_DIM / 4)   // 256 float4 lanes per row

__device__ __forceinline__ float4 fmax4(float4 a, float4 b) {
    float4 r;
    r.x = fmaxf(a.x, b.x);
    r.y = fmaxf(a.y, b.y);
    r.z = fmaxf(a.z, b.z);
    r.w = fmaxf(a.w, b.w);
    return r;
}

// Order-preserving float atomic max (stored value remains a normal float):
//  - nonneg floats: int ordering == float ordering  -> atomicMax(int)
//  - negative floats: unsigned ordering is reversed -> atomicMin(uint)
// Mixed-sign races resolve correctly in both orders.
// Init pattern 0xFFFFFFFF is an identity: as int = -1 (any v>=0 wins),
// as uint = UINT_MAX (any v<0 wins). Every column gets >=1 update (len>=1).
__device__ __forceinline__ void atomicMaxFloat(float* addr, float v) {
    int vi = __float_as_int(v);
    if (vi >= 0) {
        atomicMax((int*)addr, vi);
    } else {
        atomicMin((unsigned int*)addr, (unsigned int)vi);
    }
}

__global__ __launch_bounds__(W)
void maxpool_chunks_kernel(const float* __restrict__ ctx,
                           const int* __restrict__ begins,
                           const int* __restrict__ lens,
                           float* __restrict__ out) {
    // chunk-major: consecutive blockIdx.x = chunks of the SAME span
    const int chunk = blockIdx.x;            // 0 .. N_CHUNKS-1
    const int span  = blockIdx.y;            // 0 .. B*N_SPANS-1
    const int b     = span / N_SPANS;

    // Issue both metadata loads concurrently BEFORE any branch, so the two
    // ~600-cycle memory round trips overlap instead of serializing.
    const int begin_raw = __ldg(&begins[span]);
    int len = __ldg(&lens[span]);
    len = len < 1 ? 1 : len;

    const int start = chunk * CHUNK;
    if (start >= len) return;                // empty chunk: exit immediately
    const int rows = min(CHUNK, len - start);

    const int tid = threadIdx.x;
    const float4* base = (const float4*)(ctx + (long long)b * S_DIM * H_DIM
                                             + (long long)(begin_raw + start) * H_DIM) + tid;

    const float NEG = -CUDART_INF_F;
    float4 m0 = make_float4(NEG, NEG, NEG, NEG);
    float4 m1 = m0, m2 = m0, m3 = m0;

    int p = 0;
    // 8 independent outstanding 16B loads per thread per iteration (MLP = 8)
    for (; p + 8 <= rows; p += 8) {
        float4 v0 = __ldg(base + (p + 0) * W);
        float4 v1 = __ldg(base + (p + 1) * W);
        float4 v2 = __ldg(base + (p + 2) * W);
        float4 v3 = __ldg(base + (p + 3) * W);
        float4 v4 = __ldg(base + (p + 4) * W);
        float4 v5 = __ldg(base + (p + 5) * W);
        float4 v6 = __ldg(base + (p + 6) * W);
        float4 v7 = __ldg(base + (p + 7) * W);
        m0 = fmax4(m0, fmax4(v0, v4));
        m1 = fmax4(m1, fmax4(v1, v5));
        m2 = fmax4(m2, fmax4(v2, v6));
        m3 = fmax4(m3, fmax4(v3, v7));
    }
    if (p + 4 <= rows) {
        float4 v0 = __ldg(base + (p + 0) * W);
        float4 v1 = __ldg(base + (p + 1) * W);
        float4 v2 = __ldg(base + (p + 2) * W);
        float4 v3 = __ldg(base + (p + 3) * W);
        m0 = fmax4(m0, v0);
        m1 = fmax4(m1, v1);
        m2 = fmax4(m2, v2);
        m3 = fmax4(m3, v3);
        p += 4;
    }
    for (; p < rows; p++) {
        m0 = fmax4(m0, __ldg(base + p * W));
    }

    m0 = fmax4(m0, m1);
    m2 = fmax4(m2, m3);
    m0 = fmax4(m0, m2);

    float* o = out + (long long)span * H_DIM + tid * 4;
    atomicMaxFloat(o + 0, m0.x);
    atomicMaxFloat(o + 1, m0.y);
    atomicMaxFloat(o + 2, m0.z);
    atomicMaxFloat(o + 3, m0.w);
}

extern "C" void kernel_launch(void* const* d_in, const int* in_sizes, int n_in,
                              void* d_out, int out_size) {
    const float* ctx    = (const float*)d_in[0];   // [B, S, H] float32
    const int*   begins = (const int*)d_in[1];     // [B, N_SPANS] int32
    const int*   lens   = (const int*)d_in[2];     // [B, N_SPANS] int32
    float* out = (float*)d_out;                    // [B, N_SPANS, H] float32

    // 0xFFFFFFFF is the identity element for atomicMaxFloat above.
    cudaMemsetAsync(out, 0xFF, (size_t)B_DIM * N_SPANS * H_DIM * sizeof(float));

    dim3 grid(N_CHUNKS, B_DIM * N_SPANS);
    maxpool_chunks_kernel<<<grid, W>>>(ctx, begins, lens, out);
}

// round 9
// speedup vs baseline: 1.0133x; 1.0133x over previous
#include <cuda_runtime.h>
#include <math_constants.h>

#define B_DIM 8
#define S_DIM 4096
#define H_DIM 1024
#define N_SPANS 100
#define MAX_LEN 64
#define CHUNK 16
#define N_CHUNKS (MAX_LEN / CHUNK)   // 4

#define W (H_DIM / 4)   // 256 float4 lanes per row

__device__ __forceinline__ float4 fmax4(float4 a, float4 b) {
    float4 r;
    r.x = fmaxf(a.x, b.x);
    r.y = fmaxf(a.y, b.y);
    r.z = fmaxf(a.z, b.z);
    r.w = fmaxf(a.w, b.w);
    return r;
}

// Order-preserving float atomic max (stored value remains a normal float):
//  - nonneg floats: int ordering == float ordering  -> atomicMax(int)
//  - negative floats: unsigned ordering is reversed -> atomicMin(uint)
// Mixed-sign races resolve correctly in both orders.
// Init pattern 0xFFFFFFFF is an identity: as int = -1 (any v>=0 wins),
// as uint = UINT_MAX (any v<0 wins). Every column gets >=1 update (len>=1).
__device__ __forceinline__ void atomicMaxFloat(float* addr, float v) {
    int vi = __float_as_int(v);
    if (vi >= 0) {
        atomicMax((int*)addr, vi);
    } else {
        atomicMin((unsigned int*)addr, (unsigned int)vi);
    }
}

__global__ __launch_bounds__(W)
void maxpool_chunks_kernel(const float* __restrict__ ctx,
                           const int* __restrict__ begins,
                           const int* __restrict__ lens,
                           float* __restrict__ out) {
    // chunk-major: consecutive blockIdx.x = chunks of the SAME span
    const int chunk = blockIdx.x;            // 0 .. N_CHUNKS-1
    const int span  = blockIdx.y;            // 0 .. B*N_SPANS-1
    const int b     = span / N_SPANS;

    // Issue both metadata loads concurrently BEFORE any branch, so the two
    // ~600-cycle memory round trips overlap instead of serializing.
    const int begin_raw = __ldg(&begins[span]);
    int len = __ldg(&lens[span]);
    len = len < 1 ? 1 : len;

    const int start = chunk * CHUNK;
    if (start >= len) return;                // empty chunk: exit immediately
    const int rows = min(CHUNK, len - start);

    const int tid = threadIdx.x;
    const float4* base = (const float4*)(ctx + (long long)b * S_DIM * H_DIM
                                             + (long long)(begin_raw + start) * H_DIM) + tid;

    const float NEG = -CUDART_INF_F;
    float4 m0 = make_float4(NEG, NEG, NEG, NEG);
    float4 m1 = m0, m2 = m0, m3 = m0;

    int p = 0;
    // 8 independent outstanding 16B loads per thread per iteration (MLP = 8)
    for (; p + 8 <= rows; p += 8) {
        float4 v0 = __ldg(base + (p + 0) * W);
        float4 v1 = __ldg(base + (p + 1) * W);
        float4 v2 = __ldg(base + (p + 2) * W);
        float4 v3 = __ldg(base + (p + 3) * W);
        float4 v4 = __ldg(base + (p + 4) * W);
        float4 v5 = __ldg(base + (p + 5) * W);
        float4 v6 = __ldg(base + (p + 6) * W);
        float4 v7 = __ldg(base + (p + 7) * W);
        m0 = fmax4(m0, fmax4(v0, v4));
        m1 = fmax4(m1, fmax4(v1, v5));
        m2 = fmax4(m2, fmax4(v2, v6));
        m3 = fmax4(m3, fmax4(v3, v7));
    }
    if (p + 4 <= rows) {
        float4 v0 = __ldg(base + (p + 0) * W);
        float4 v1 = __ldg(base + (p + 1) * W);
        float4 v2 = __ldg(base + (p + 2) * W);
        float4 v3 = __ldg(base + (p + 3) * W);
        m0 = fmax4(m0, v0);
        m1 = fmax4(m1, v1);
        m2 = fmax4(m2, v2);
        m3 = fmax4(m3, v3);
        p += 4;
    }
    for (; p < rows; p++) {
        m0 = fmax4(m0, __ldg(base + p * W));
    }

    m0 = fmax4(m0, m1);
    m2 = fmax4(m2, m3);
    m0 = fmax4(m0, m2);

    float* o = out + (long long)span * H_DIM + tid * 4;
    atomicMaxFloat(o + 0, m0.x);
    atomicMaxFloat(o + 1, m0.y);
    atomicMaxFloat(o + 2, m0.z);
    atomicMaxFloat(o + 3, m0.w);
}

extern "C" void kernel_launch(void* const* d_in, const int* in_sizes, int n_in,
                              void* d_out, int out_size) {
    const float* ctx    = (const float*)d_in[0];   // [B, S, H] float32
    const int*   begins = (const int*)d_in[1];     // [B, N_SPANS] int32
    const int*   lens   = (const int*)d_in[2];     // [B, N_SPANS] int32
    float* out = (float*)d_out;                    // [B, N_SPANS, H] float32

    // 0xFFFFFFFF is the identity element for atomicMaxFloat above.
    cudaMemsetAsync(out, 0xFF, (size_t)B_DIM * N_SPANS * H_DIM * sizeof(float));

    dim3 grid(N_CHUNKS, B_DIM * N_SPANS);
    maxpool_chunks_kernel<<<grid, W>>>(ctx, begins, lens, out);
}

// round 10
// speedup vs baseline: 1.0152x; 1.0019x over previous
#include <cuda_runtime.h>
#include <math_constants.h>

#define B_DIM 8
#define S_DIM 4096
#define H_DIM 1024
#define N_SPANS 100
#define MAX_LEN 64
#define CHUNK 16
#define N_CHUNKS (MAX_LEN / CHUNK)   // 4

#define W (H_DIM / 4)   // 256 float4 lanes per row

__device__ __forceinline__ float4 fmax4(float4 a, float4 b) {
    float4 r;
    r.x = fmaxf(a.x, b.x);
    r.y = fmaxf(a.y, b.y);
    r.z = fmaxf(a.z, b.z);
    r.w = fmaxf(a.w, b.w);
    return r;
}

// Order-preserving float atomic max (stored value remains a normal float):
//  - nonneg floats: int ordering == float ordering  -> atomicMax(int)
//  - negative floats: unsigned ordering is reversed -> atomicMin(uint)
// Mixed-sign races resolve correctly in both orders.
// Init pattern 0xFFFFFFFF is an identity: as int = -1 (any v>=0 wins),
// as uint = UINT_MAX (any v<0 wins). Every column gets >=1 update (len>=1).
__device__ __forceinline__ void atomicMaxFloat(float* addr, float v) {
    int vi = __float_as_int(v);
    if (vi >= 0) {
        atomicMax((int*)addr, vi);
    } else {
        atomicMin((unsigned int*)addr, (unsigned int)vi);
    }
}

__global__ __launch_bounds__(W)
void maxpool_chunks_kernel(const float* __restrict__ ctx,
                           const int* __restrict__ begins,
                           const int* __restrict__ lens,
                           float* __restrict__ out) {
    // chunk-major: consecutive blockIdx.x = chunks of the SAME span
    const int chunk = blockIdx.x;            // 0 .. N_CHUNKS-1
    const int span  = blockIdx.y;            // 0 .. B*N_SPANS-1
    const int b     = span / N_SPANS;

    // Issue both metadata loads concurrently BEFORE any branch, so the two
    // ~600-cycle memory round trips overlap instead of serializing.
    const int begin_raw = __ldg(&begins[span]);
    int len = __ldg(&lens[span]);
    len = len < 1 ? 1 : len;

    const int start = chunk * CHUNK;
    if (start >= len) return;                // empty chunk: exit immediately
    const int rows = min(CHUNK, len - start);

    const int tid = threadIdx.x;
    const float4* base = (const float4*)(ctx + (long long)b * S_DIM * H_DIM
                                             + (long long)(begin_raw + start) * H_DIM) + tid;

    const float NEG = -CUDART_INF_F;
    float4 m0 = make_float4(NEG, NEG, NEG, NEG);
    float4 m1 = m0, m2 = m0, m3 = m0;

    int p = 0;
    // 8 independent outstanding 16B loads per thread per iteration (MLP = 8)
    for (; p + 8 <= rows; p += 8) {
        float4 v0 = __ldg(base + (p + 0) * W);
        float4 v1 = __ldg(base + (p + 1) * W);
        float4 v2 = __ldg(base + (p + 2) * W);
        float4 v3 = __ldg(base + (p + 3) * W);
        float4 v4 = __ldg(base + (p + 4) * W);
        float4 v5 = __ldg(base + (p + 5) * W);
        float4 v6 = __ldg(base + (p + 6) * W);
        float4 v7 = __ldg(base + (p + 7) * W);
        m0 = fmax4(m0, fmax4(v0, v4));
        m1 = fmax4(m1, fmax4(v1, v5));
        m2 = fmax4(m2, fmax4(v2, v6));
        m3 = fmax4(m3, fmax4(v3, v7));
    }
    if (p + 4 <= rows) {
        float4 v0 = __ldg(base + (p + 0) * W);
        float4 v1 = __ldg(base + (p + 1) * W);
        float4 v2 = __ldg(base + (p + 2) * W);
        float4 v3 = __ldg(base + (p + 3) * W);
        m0 = fmax4(m0, v0);
        m1 = fmax4(m1, v1);
        m2 = fmax4(m2, v2);
        m3 = fmax4(m3, v3);
        p += 4;
    }
    for (; p < rows; p++) {
        m0 = fmax4(m0, __ldg(base + p * W));
    }

    m0 = fmax4(m0, m1);
    m2 = fmax4(m2, m3);
    m0 = fmax4(m0, m2);

    float* o = out + (long long)span * H_DIM + tid * 4;
    atomicMaxFloat(o + 0, m0.x);
    atomicMaxFloat(o + 1, m0.y);
    atomicMaxFloat(o + 2, m0.z);
    atomicMaxFloat(o + 3, m0.w);
}

extern "C" void kernel_launch(void* const* d_in, const int* in_sizes, int n_in,
                              void* d_out, int out_size) {
    const float* ctx    = (const float*)d_in[0];   // [B, S, H] float32
    const int*   begins = (const int*)d_in[1];     // [B, N_SPANS] int32
    const int*   lens   = (const int*)d_in[2];     // [B, N_SPANS] int32
    float* out = (float*)d_out;                    // [B, N_SPANS, H] float32

    // 0xFFFFFFFF is the identity element for atomicMaxFloat above.
    cudaMemsetAsync(out, 0xFF, (size_t)B_DIM * N_SPANS * H_DIM * sizeof(float));

    dim3 grid(N_CHUNKS, B_DIM * N_SPANS);
    maxpool_chunks_kernel<<<grid, W>>>(ctx, begins, lens, out);
}